// round 15
// baseline (speedup 1.0000x reference)
#include <cuda_runtime.h>
#include <cuda_fp16.h>
#include <cstdint>

#define DEVI __device__ __forceinline__

// ---------------------------------------------------------------------------
// Problem constants
// ---------------------------------------------------------------------------
namespace cfg {
constexpr int BROWS = 512;      // batch (GEMM M)
constexpr int DIM   = 512;      // embedding dim (GEMM K)
constexpr int NCLS  = 200000;   // classes (GEMM N, tiled)
constexpr int NT    = 128;      // classes per CTA tile
constexpr int NTILE = (NCLS + NT - 1) / NT;   // 1563
constexpr int FULLT = 1480;                   // tiles done by single CTAs
constexpr int GRID2 = FULLT + 2 * (NTILE - FULLT);  // 1646

// smem layout (bytes, within dynamic smem)
constexpr int SM_INV = 0;                     // 128 floats: 1/||w||
constexpr int SM_B   = 1024;                  // 8 K-slices x 128 rows x 128B f16
constexpr int SM_A   = SM_B + 131072;         // 2 bufs x 128 rows x 128B f16
constexpr int SM_W   = SM_A + 32768;          // 2 bufs x 128 rows x 256B fp32
constexpr int SM_TOT = SM_W + 65536;          // 230400

constexpr float S_LOG2E = 92.33248261689366f; // 64 * log2(e)
}

// ---------------------------------------------------------------------------
// Device scratch (no allocations allowed)
// ---------------------------------------------------------------------------
__device__ __align__(16) float  g_en32[cfg::BROWS * cfg::DIM]; // norm emb fp32
__device__ __align__(16) __half g_en16[cfg::BROWS * cfg::DIM]; // norm emb fp16
__device__ float g_rowsum[cfg::BROWS];   // sum exp(l-64), excl target
__device__ float g_tgt[cfg::BROWS];      // exact fp32 target cosine
__device__ float g_invn;                 // 1/n_valid

// ---------------------------------------------------------------------------
// PTX helpers (base-ISA only: legal on sm_103 / compute_103)
// ---------------------------------------------------------------------------
DEVI uint32_t smem_u32(const void* p) {
    uint32_t a;
    asm("{ .reg .u64 t; cvta.to.shared.u64 t, %1; cvt.u32.u64 %0, t; }"
        : "=r"(a) : "l"(p));
    return a;
}

DEVI float ex2_approx(float x) {
    float r;
    asm("ex2.approx.ftz.f32 %0, %1;" : "=f"(r) : "f"(x));
    return r;
}

DEVI void cp_async16(uint32_t dst, const void* src) {
    asm volatile("cp.async.cg.shared.global [%0], [%1], 16;"
                 :: "r"(dst), "l"(src) : "memory");
}
DEVI void cp_async16z(uint32_t dst, const void* src, uint32_t nbytes) {
    asm volatile("cp.async.cg.shared.global [%0], [%1], 16, %2;"
                 :: "r"(dst), "l"(src), "r"(nbytes) : "memory");
}
DEVI void cp_commit() { asm volatile("cp.async.commit_group;" ::: "memory"); }
template <int N> DEVI void cp_wait() {
    asm volatile("cp.async.wait_group %0;" :: "n"(N) : "memory");
}

DEVI void ldsm_x4(uint32_t& r0, uint32_t& r1, uint32_t& r2, uint32_t& r3,
                  uint32_t addr) {
    asm volatile("ldmatrix.sync.aligned.m8n8.x4.shared.b16 {%0,%1,%2,%3}, [%4];"
                 : "=r"(r0), "=r"(r1), "=r"(r2), "=r"(r3) : "r"(addr));
}

// fp16 tensor-core MMA with fp16 accumulate
DEVI void mma16816_f16(uint32_t* d, uint32_t a0, uint32_t a1, uint32_t a2,
                       uint32_t a3, uint32_t b0, uint32_t b1) {
    asm volatile(
        "mma.sync.aligned.m16n8k16.row.col.f16.f16.f16.f16 "
        "{%0,%1}, {%2,%3,%4,%5}, {%6,%7}, {%0,%1};"
        : "+r"(d[0]), "+r"(d[1])
        : "r"(a0), "r"(a1), "r"(a2), "r"(a3), "r"(b0), "r"(b1));
}

// ---------------------------------------------------------------------------
// Kernel 1 (grid 72):
//   blocks 0..63 : normalize embeddings -> fp32 + fp16 copies (warp per row);
//                  block 0 also zeroes rowsums + counts valid labels.
//   blocks 64..71: exact fp32 target cosine g_tgt[r] = (e.w)/(||e|| ||w||)
//                  straight from raw inputs (8 rows per warp) — runs on idle
//                  SMs concurrently with the normalize blocks.
// ---------------------------------------------------------------------------
__global__ void k1_norm(const float* __restrict__ emb,
                        const float* __restrict__ W,
                        const int* __restrict__ labels) {
    __shared__ int part[8];
    int lid = threadIdx.x & 31;

    if (blockIdx.x >= 64) {
        // ---- target-cosine blocks ----
        int rbase = (blockIdx.x - 64) * 64 + (threadIdx.x >> 5) * 8;
        for (int r = rbase; r < rbase + 8; r++) {
            int lb = labels[r];
            if (lb < 0) continue;
            const float4* er = reinterpret_cast<const float4*>(emb) + (size_t)r * 128;
            const float4* wr = reinterpret_cast<const float4*>(W) + (size_t)lb * 128;
            float dot = 0.0f, ee = 0.0f, ww = 0.0f;
#pragma unroll
            for (int j = 0; j < 4; j++) {
                float4 e = er[j * 32 + lid];
                float4 w = wr[j * 32 + lid];
                dot += e.x * w.x + e.y * w.y + e.z * w.z + e.w * w.w;
                ee  += e.x * e.x + e.y * e.y + e.z * e.z + e.w * e.w;
                ww  += w.x * w.x + w.y * w.y + w.z * w.z + w.w * w.w;
            }
#pragma unroll
            for (int s = 16; s > 0; s >>= 1) {
                dot += __shfl_xor_sync(0xffffffffu, dot, s);
                ee  += __shfl_xor_sync(0xffffffffu, ee, s);
                ww  += __shfl_xor_sync(0xffffffffu, ww, s);
            }
            if (lid == 0) {
                float ne = fmaxf(sqrtf(ee), 1e-12f);
                float nw = fmaxf(sqrtf(ww), 1e-12f);
                g_tgt[r] = dot / (ne * nw);
            }
        }
        return;
    }

    // ---- normalize blocks ----
    int gw = blockIdx.x * 8 + (threadIdx.x >> 5);
    const float4* src = reinterpret_cast<const float4*>(emb) + (size_t)gw * 128;
    float4 v[4];
    float ss = 0.0f;
#pragma unroll
    for (int j = 0; j < 4; j++) {
        v[j] = src[j * 32 + lid];
        ss += v[j].x * v[j].x + v[j].y * v[j].y + v[j].z * v[j].z + v[j].w * v[j].w;
    }
#pragma unroll
    for (int s = 16; s > 0; s >>= 1) ss += __shfl_xor_sync(0xffffffffu, ss, s);
    float inv = 1.0f / fmaxf(sqrtf(ss), 1e-12f);

    float4* d32 = reinterpret_cast<float4*>(g_en32) + (size_t)gw * 128;
    uint2*  d16 = reinterpret_cast<uint2*>(g_en16) + (size_t)gw * 128;
#pragma unroll
    for (int j = 0; j < 4; j++) {
        float4 n = make_float4(v[j].x * inv, v[j].y * inv, v[j].z * inv, v[j].w * inv);
        d32[j * 32 + lid] = n;
        __half2 h0 = __float22half2_rn(make_float2(n.x, n.y));
        __half2 h1 = __float22half2_rn(make_float2(n.z, n.w));
        uint2 pk;
        pk.x = *reinterpret_cast<uint32_t*>(&h0);
        pk.y = *reinterpret_cast<uint32_t*>(&h1);
        d16[j * 32 + lid] = pk;
    }

    // ---- fused prep (block 0 only) ----
    if (blockIdx.x == 0) {
        int t = threadIdx.x;
        g_rowsum[t] = 0.0f;
        g_rowsum[t + 256] = 0.0f;
        int c = (labels[t] >= 0) + (labels[t + 256] >= 0);
#pragma unroll
        for (int s = 16; s > 0; s >>= 1) c += __shfl_xor_sync(0xffffffffu, c, s);
        if (lid == 0) part[t >> 5] = c;
        __syncthreads();
        if (t == 0) {
            int tot = 0;
#pragma unroll
            for (int j = 0; j < 8; j++) tot += part[j];
            g_invn = 1.0f / fmaxf((float)tot, 1.0f);
        }
    }
}

// ---------------------------------------------------------------------------
// Kernel 2: fused fp16 mma.sync (f16 acc) GEMM + softmax-denominator
// epilogue, with tail-wave splitting — BYTE-IDENTICAL to the verified
// 379.6us kernel (do not touch; epilogue changes regress scheduling):
//   bid <  FULLT : tile bid, slices 0..31 (all 4 M-chunks)
//   bid >= FULLT : j = bid-FULLT; tile FULLT + j/2; s0 = (j&1)*16; 16 slices
// ---------------------------------------------------------------------------
__global__ void __launch_bounds__(256, 1)
k2_gemm(const float* __restrict__ W, const int* __restrict__ labels) {
    extern __shared__ __align__(1024) char smem[];
    const uint32_t sb = smem_u32(smem);
    const int tid = threadIdx.x;
    const int wid = tid >> 5;
    const int lid = tid & 31;
    const int wm  = wid & 3;        // warp M index (4 x 32 rows per chunk)
    const int wn  = wid >> 2;       // warp N index (2 x 64 classes)

    int tile, s0, nsl;
    if ((int)blockIdx.x < cfg::FULLT) {
        tile = blockIdx.x;  s0 = 0;  nsl = 32;
    } else {
        int j = blockIdx.x - cfg::FULLT;
        tile = cfg::FULLT + (j >> 1);
        s0   = (j & 1) << 4;          // 0 or 16
        nsl  = 16;
    }
    const int cls0 = tile * cfg::NT;
    const int mc0  = s0 >> 3;         // first M-chunk (0 or 2)

    float* sinv = reinterpret_cast<float*>(smem + cfg::SM_INV);

    // ---- prologue: stage A slice s0 + W slice 0 (one commit group) ----
    {
        const char* gsrc = reinterpret_cast<const char*>(g_en16);
#pragma unroll
        for (int q = 0; q < 4; q++) {
            int idx = q * 256 + tid;           // 16B chunk id, 0..1023
            int row = idx >> 3, c8 = idx & 7;
            uint32_t dst = sb + cfg::SM_A + (uint32_t)row * 128
                         + (uint32_t)((c8 ^ (row & 7)) << 4);
            cp_async16(dst, gsrc + ((size_t)(mc0 * 128 + row) * 512 + c8 * 8) * 2);
        }
#pragma unroll
        for (int q = 0; q < 8; q++) {
            int g = q * 256 + tid;             // 16B chunk id, 0..2047
            int row = g >> 4, c = g & 15;
            int cls = cls0 + row;
            bool ok = (cls < cfg::NCLS);
            uint32_t dst = sb + cfg::SM_W + (uint32_t)row * 256
                         + (uint32_t)((c ^ (row & 15)) << 4);
            const float* src = W + (size_t)(ok ? cls : 0) * 512 + c * 4;
            cp_async16z(dst, src, ok ? 16u : 0u);
        }
        cp_commit();
    }

    float wss = 0.0f;      // partial sum-sq: row tid>>1, half tid&1
    uint32_t acc[2][8][2]; // f16x2 accumulators: [mt][nt][row r / r+8]
#pragma unroll
    for (int a = 0; a < 2; a++)
#pragma unroll
        for (int b = 0; b < 8; b++) {
            acc[a][b][0] = 0u; acc[a][b][1] = 0u;
        }

    const int grp = lid >> 2;      // 0..7 (row within 8)
    const int qid = lid & 3;       // quad lane

    // ---- Mainloop: nsl slices (local s; global slice i = s0 + s) ----
    for (int s = 0; s < nsl; s++) {
        const int i  = s0 + s;
        const int kc = i & 7;

        // issue commit group: A slice i+1 (+ W k-slice s+1 while s<7)
        if (s + 1 < nsl) {
            int i2 = i + 1;
            int mc2 = i2 >> 3, kk2 = i2 & 7, bb = i2 & 1;
            const char* gsrc = reinterpret_cast<const char*>(g_en16);
#pragma unroll
            for (int q = 0; q < 4; q++) {
                int idx = q * 256 + tid;
                int row = idx >> 3, c8 = idx & 7;
                uint32_t dst = sb + cfg::SM_A + (uint32_t)bb * 16384
                             + (uint32_t)row * 128
                             + (uint32_t)((c8 ^ (row & 7)) << 4);
                size_t gofs = ((size_t)(mc2 * 128 + row) * 512 + kk2 * 64 + c8 * 8) * 2;
                cp_async16(dst, gsrc + gofs);
            }
            if (s < 7) {
                int ks = s + 1;                 // W k-slice to stage
#pragma unroll
                for (int q = 0; q < 8; q++) {
                    int g = q * 256 + tid;
                    int row = g >> 4, c = g & 15;
                    int cls = cls0 + row;
                    bool ok = (cls < cfg::NCLS);
                    uint32_t dst = sb + cfg::SM_W + (uint32_t)(ks & 1) * 32768
                                 + (uint32_t)row * 256
                                 + (uint32_t)((c ^ (row & 15)) << 4);
                    const float* src = W + (size_t)(ok ? cls : 0) * 512 + ks * 64 + c * 4;
                    cp_async16z(dst, src, ok ? 16u : 0u);
                }
            }
            cp_commit();
            cp_wait<1>();          // previous group (A slice i, W slice s) in
        } else {
            cp_wait<0>();
        }
        __syncthreads();

        // ---- first 8 local slices: convert staged fp32 W -> fp16 B ----
        if (s < 8) {
            const int row = tid >> 1;
            const int hh  = tid & 1;               // half: k [32h, 32h+32)
            const char* wbase = smem + cfg::SM_W + (size_t)(s & 1) * 32768
                              + (size_t)row * 256;
            char* bbase = smem + cfg::SM_B + (size_t)s * 16384 + (size_t)row * 128;
#pragma unroll
            for (int j = 0; j < 8; j++) {
                int c = hh * 8 + j;
                float4 v = *reinterpret_cast<const float4*>(
                    wbase + ((c ^ (row & 15)) << 4));
                wss += v.x * v.x + v.y * v.y + v.z * v.z + v.w * v.w;
                __half2 h0 = __float22half2_rn(make_float2(v.x, v.y));
                __half2 h1 = __float22half2_rn(make_float2(v.z, v.w));
                uint2 pk;
                pk.x = *reinterpret_cast<uint32_t*>(&h0);
                pk.y = *reinterpret_cast<uint32_t*>(&h1);
                *reinterpret_cast<uint2*>(
                    bbase + (((c >> 1) ^ (row & 7)) << 4) + (c & 1) * 8) = pk;
            }
            if (s == 7) {
                float tot = wss + __shfl_xor_sync(0xffffffffu, wss, 1);
                if (hh == 0)
                    sinv[row] = 1.0f / fmaxf(sqrtf(tot), 1e-12f);
            }
            __syncthreads();       // B slice s (and sinv at s=7) visible
        }

        const uint32_t abase = sb + cfg::SM_A + (uint32_t)(i & 1) * 16384;
        const uint32_t bbase = sb + cfg::SM_B + (uint32_t)kc * 16384;

#pragma unroll
        for (int kt = 0; kt < 4; kt++) {       // four k16 steps per 64-K slice
            // A fragments: 2 m-tiles of 16x16
            uint32_t af[2][4];
#pragma unroll
            for (int mt = 0; mt < 2; mt++) {
                int row = wm * 32 + mt * 16 + (lid & 15);
                int c8  = (kt * 2 + (lid >> 4)) ^ (row & 7);
                ldsm_x4(af[mt][0], af[mt][1], af[mt][2], af[mt][3],
                        abase + (uint32_t)row * 128 + (uint32_t)(c8 << 4));
            }
            // B fragments: 4 n-tile-pairs of (16 n x 16 k)
            uint32_t bf[4][4];
#pragma unroll
            for (int np = 0; np < 4; np++) {
                int n   = np * 16 + ((lid >> 4) << 3) + (lid & 7);
                int row = wn * 64 + n;
                int c8  = (kt * 2 + ((lid >> 3) & 1)) ^ (row & 7);
                ldsm_x4(bf[np][0], bf[np][1], bf[np][2], bf[np][3],
                        bbase + (uint32_t)row * 128 + (uint32_t)(c8 << 4));
            }
#pragma unroll
            for (int mt = 0; mt < 2; mt++)
#pragma unroll
                for (int np = 0; np < 4; np++) {
                    mma16816_f16(acc[mt][np * 2],
                                 af[mt][0], af[mt][1], af[mt][2], af[mt][3],
                                 bf[np][0], bf[np][1]);
                    mma16816_f16(acc[mt][np * 2 + 1],
                                 af[mt][0], af[mt][1], af[mt][2], af[mt][3],
                                 bf[np][2], bf[np][3]);
                }
        }
        __syncthreads();           // all reads of A buf[i&1] done

        // ---- per-M-chunk epilogue ----
        if (kc == 7) {
            int mc = i >> 3;
            int row0 = mc * 128 + wm * 32 + grp;   // rows row0(+mt*16), +8
#pragma unroll
            for (int mt = 0; mt < 2; mt++) {
                int ra = row0 + mt * 16;
                int rb = ra + 8;
                int la  = labels[ra];
                int lbv = labels[rb];
                float sa = 0.0f, sbv = 0.0f;
#pragma unroll
                for (int nt = 0; nt < 8; nt++) {
                    int lc = wn * 64 + nt * 8 + qid * 2;
                    float2 iv = *reinterpret_cast<const float2*>(sinv + lc);
                    int cbase = cls0 + lc;
                    float2 va = __half22float2(
                        *reinterpret_cast<__half2*>(&acc[mt][nt][0]));
                    float2 vb = __half22float2(
                        *reinterpret_cast<__half2*>(&acc[mt][nt][1]));
#pragma unroll
                    for (int h = 0; h < 2; h++) {
                        int cls = cbase + h;
                        float ivv = h ? iv.y : iv.x;
                        bool oob = (cls >= cfg::NCLS);
                        float c0 = (h ? va.y : va.x) * ivv;
                        float c2 = (h ? vb.y : vb.x) * ivv;
                        c0 = fminf(fmaxf(c0, -1.0f), 1.0f);
                        c2 = fminf(fmaxf(c2, -1.0f), 1.0f);
                        float e0 = ex2_approx(fmaf(c0, cfg::S_LOG2E, -cfg::S_LOG2E));
                        float e2 = ex2_approx(fmaf(c2, cfg::S_LOG2E, -cfg::S_LOG2E));
                        sa  += (oob || cls == la)  ? 0.0f : e0;
                        sbv += (oob || cls == lbv) ? 0.0f : e2;
                    }
                }
                sa  += __shfl_xor_sync(0xffffffffu, sa, 1);
                sa  += __shfl_xor_sync(0xffffffffu, sa, 2);
                sbv += __shfl_xor_sync(0xffffffffu, sbv, 1);
                sbv += __shfl_xor_sync(0xffffffffu, sbv, 2);
                if (qid == 0) {
                    atomicAdd(&g_rowsum[ra], sa);
                    atomicAdd(&g_rowsum[rb], sbv);
                }
            }
#pragma unroll
            for (int a = 0; a < 2; a++)
#pragma unroll
                for (int b = 0; b < 8; b++) {
                    acc[a][b][0] = 0u; acc[a][b][1] = 0u;
                }
        }
    }
}

// ---------------------------------------------------------------------------
// Kernel 3: finalize — arcface margin on precomputed exact fp32 target +
// single-block loss reduction.
// ---------------------------------------------------------------------------
__global__ void k3_fin(const int* __restrict__ labels,
                       float* __restrict__ out) {
    __shared__ float red[512];
    int r = threadIdx.x;
    int lb = labels[r];
    float nll = 0.0f;
    if (lb >= 0) {
        float tgt = fminf(fmaxf(g_tgt[r], -1.0f), 1.0f);
        float th  = acosf(fminf(fmaxf(tgt, -1.0f + 1e-7f), 1.0f - 1e-7f));
        float nt  = cosf(th + 0.5f);                       // cos(theta + m)
        float et  = exp2f(fmaf(nt, cfg::S_LOG2E, -cfg::S_LOG2E));
        float se  = g_rowsum[r] + et;                      // full shifted sum
        nll = 64.0f + logf(se) - 64.0f * nt;               // lse - target logit
    }
    red[r] = nll;
    __syncthreads();
#pragma unroll
    for (int s = 256; s > 0; s >>= 1) {
        if (r < s) red[r] += red[r + s];
        __syncthreads();
    }
    if (r == 0) out[0] = red[0] * g_invn;
}

// ---------------------------------------------------------------------------
// Launch
// ---------------------------------------------------------------------------
extern "C" void kernel_launch(void* const* d_in, const int* in_sizes, int n_in,
                              void* d_out, int out_size) {
    const float* emb    = (const float*)d_in[0];
    const int*   labels = (const int*)d_in[1];
    const float* W      = (const float*)d_in[2];
    float*       out    = (float*)d_out;

    cudaFuncSetAttribute(k2_gemm, cudaFuncAttributeMaxDynamicSharedMemorySize,
                         cfg::SM_TOT);

    k1_norm<<<72, 256>>>(emb, W, labels);
    k2_gemm<<<cfg::GRID2, 256, cfg::SM_TOT>>>(W, labels);
    k3_fin<<<1, 512>>>(labels, out);
}

// round 16
// speedup vs baseline: 1.0222x; 1.0222x over previous
#include <cuda_runtime.h>
#include <cuda_fp16.h>
#include <cstdint>

#define DEVI __device__ __forceinline__

// ---------------------------------------------------------------------------
// Problem constants
// ---------------------------------------------------------------------------
namespace cfg {
constexpr int BROWS = 512;      // batch (GEMM M)
constexpr int DIM   = 512;      // embedding dim (GEMM K)
constexpr int NCLS  = 200000;   // classes (GEMM N, tiled)
constexpr int NT    = 128;      // classes per CTA tile
constexpr int NTILE = (NCLS + NT - 1) / NT;   // 1563
constexpr int FULLT = 1480;                   // tiles done by single CTAs
constexpr int GRID2 = FULLT + 2 * (NTILE - FULLT);  // 1646

// smem layout (bytes, within dynamic smem)
constexpr int SM_INV = 0;                     // 128 floats: 1/||w||
constexpr int SM_B   = 1024;                  // 8 K-slices x 128 rows x 128B f16
constexpr int SM_A   = SM_B + 131072;         // 2 bufs x 128 rows x 128B f16
constexpr int SM_W   = SM_A + 32768;          // 2 bufs x 128 rows x 256B fp32
constexpr int SM_TOT = SM_W + 65536;          // 230400

constexpr float S_LOG2E = 92.33248261689366f; // 64 * log2(e)
}

// ---------------------------------------------------------------------------
// Device scratch (no allocations allowed)
// ---------------------------------------------------------------------------
__device__ __align__(16) float  g_en32[cfg::BROWS * cfg::DIM]; // norm emb fp32
__device__ __align__(16) __half g_en16[cfg::BROWS * cfg::DIM]; // norm emb fp16
__device__ float g_rowsum[cfg::BROWS];   // sum exp(l-64), excl target
__device__ float g_tgt[cfg::BROWS];      // exact fp32 target cosine
__device__ float g_invn;                 // 1/n_valid

// ---------------------------------------------------------------------------
// PTX helpers (base-ISA only: legal on sm_103 / compute_103)
// ---------------------------------------------------------------------------
DEVI uint32_t smem_u32(const void* p) {
    uint32_t a;
    asm("{ .reg .u64 t; cvta.to.shared.u64 t, %1; cvt.u32.u64 %0, t; }"
        : "=r"(a) : "l"(p));
    return a;
}

DEVI float ex2_approx(float x) {
    float r;
    asm("ex2.approx.ftz.f32 %0, %1;" : "=f"(r) : "f"(x));
    return r;
}

DEVI void cp_async16(uint32_t dst, const void* src) {
    asm volatile("cp.async.cg.shared.global [%0], [%1], 16;"
                 :: "r"(dst), "l"(src) : "memory");
}
DEVI void cp_async16z(uint32_t dst, const void* src, uint32_t nbytes) {
    asm volatile("cp.async.cg.shared.global [%0], [%1], 16, %2;"
                 :: "r"(dst), "l"(src), "r"(nbytes) : "memory");
}
DEVI void cp_commit() { asm volatile("cp.async.commit_group;" ::: "memory"); }
template <int N> DEVI void cp_wait() {
    asm volatile("cp.async.wait_group %0;" :: "n"(N) : "memory");
}

DEVI void ldsm_x4(uint32_t& r0, uint32_t& r1, uint32_t& r2, uint32_t& r3,
                  uint32_t addr) {
    asm volatile("ldmatrix.sync.aligned.m8n8.x4.shared.b16 {%0,%1,%2,%3}, [%4];"
                 : "=r"(r0), "=r"(r1), "=r"(r2), "=r"(r3) : "r"(addr));
}

// fp16 tensor-core MMA with fp16 accumulate
DEVI void mma16816_f16(uint32_t* d, uint32_t a0, uint32_t a1, uint32_t a2,
                       uint32_t a3, uint32_t b0, uint32_t b1) {
    asm volatile(
        "mma.sync.aligned.m16n8k16.row.col.f16.f16.f16.f16 "
        "{%0,%1}, {%2,%3,%4,%5}, {%6,%7}, {%0,%1};"
        : "+r"(d[0]), "+r"(d[1])
        : "r"(a0), "r"(a1), "r"(a2), "r"(a3), "r"(b0), "r"(b1));
}

// ---------------------------------------------------------------------------
// Kernel 1 (grid 128):
//   blocks 0..63  : normalize embeddings -> fp32 + fp16 copies (warp per row);
//                   block 0 also zeroes rowsums + counts valid labels.
//   blocks 64..127: exact fp32 target cosine g_tgt[r] = (e.w)/(||e|| ||w||)
//                   straight from raw inputs, ONE row per warp (512 warps
//                   total -> fully latency-parallel, hidden under blocks
//                   0..63 on the 148-SM chip).
// ---------------------------------------------------------------------------
__global__ void k1_norm(const float* __restrict__ emb,
                        const float* __restrict__ W,
                        const int* __restrict__ labels) {
    __shared__ int part[8];
    int lid = threadIdx.x & 31;

    if (blockIdx.x >= 64) {
        // ---- target-cosine blocks: one row per warp ----
        int r = (blockIdx.x - 64) * 8 + (threadIdx.x >> 5);
        int lb = labels[r];
        if (lb < 0) return;
        const float4* er = reinterpret_cast<const float4*>(emb) + (size_t)r * 128;
        const float4* wr = reinterpret_cast<const float4*>(W) + (size_t)lb * 128;
        float dot = 0.0f, ee = 0.0f, ww = 0.0f;
#pragma unroll
        for (int j = 0; j < 4; j++) {
            float4 e = er[j * 32 + lid];
            float4 w = wr[j * 32 + lid];
            dot += e.x * w.x + e.y * w.y + e.z * w.z + e.w * w.w;
            ee  += e.x * e.x + e.y * e.y + e.z * e.z + e.w * e.w;
            ww  += w.x * w.x + w.y * w.y + w.z * w.z + w.w * w.w;
        }
#pragma unroll
        for (int s = 16; s > 0; s >>= 1) {
            dot += __shfl_xor_sync(0xffffffffu, dot, s);
            ee  += __shfl_xor_sync(0xffffffffu, ee, s);
            ww  += __shfl_xor_sync(0xffffffffu, ww, s);
        }
        if (lid == 0) {
            float ne = fmaxf(sqrtf(ee), 1e-12f);
            float nw = fmaxf(sqrtf(ww), 1e-12f);
            g_tgt[r] = dot / (ne * nw);
        }
        return;
    }

    // ---- normalize blocks ----
    int gw = blockIdx.x * 8 + (threadIdx.x >> 5);
    const float4* src = reinterpret_cast<const float4*>(emb) + (size_t)gw * 128;
    float4 v[4];
    float ss = 0.0f;
#pragma unroll
    for (int j = 0; j < 4; j++) {
        v[j] = src[j * 32 + lid];
        ss += v[j].x * v[j].x + v[j].y * v[j].y + v[j].z * v[j].z + v[j].w * v[j].w;
    }
#pragma unroll
    for (int s = 16; s > 0; s >>= 1) ss += __shfl_xor_sync(0xffffffffu, ss, s);
    float inv = 1.0f / fmaxf(sqrtf(ss), 1e-12f);

    float4* d32 = reinterpret_cast<float4*>(g_en32) + (size_t)gw * 128;
    uint2*  d16 = reinterpret_cast<uint2*>(g_en16) + (size_t)gw * 128;
#pragma unroll
    for (int j = 0; j < 4; j++) {
        float4 n = make_float4(v[j].x * inv, v[j].y * inv, v[j].z * inv, v[j].w * inv);
        d32[j * 32 + lid] = n;
        __half2 h0 = __float22half2_rn(make_float2(n.x, n.y));
        __half2 h1 = __float22half2_rn(make_float2(n.z, n.w));
        uint2 pk;
        pk.x = *reinterpret_cast<uint32_t*>(&h0);
        pk.y = *reinterpret_cast<uint32_t*>(&h1);
        d16[j * 32 + lid] = pk;
    }

    // ---- fused prep (block 0 only) ----
    if (blockIdx.x == 0) {
        int t = threadIdx.x;
        g_rowsum[t] = 0.0f;
        g_rowsum[t + 256] = 0.0f;
        int c = (labels[t] >= 0) + (labels[t + 256] >= 0);
#pragma unroll
        for (int s = 16; s > 0; s >>= 1) c += __shfl_xor_sync(0xffffffffu, c, s);
        if (lid == 0) part[t >> 5] = c;
        __syncthreads();
        if (t == 0) {
            int tot = 0;
#pragma unroll
            for (int j = 0; j < 8; j++) tot += part[j];
            g_invn = 1.0f / fmaxf((float)tot, 1.0f);
        }
    }
}

// ---------------------------------------------------------------------------
// Kernel 2: fused fp16 mma.sync (f16 acc) GEMM + softmax-denominator
// epilogue, with tail-wave splitting — BYTE-IDENTICAL to the verified
// 379.6us kernel (do not touch; epilogue changes regress scheduling):
//   bid <  FULLT : tile bid, slices 0..31 (all 4 M-chunks)
//   bid >= FULLT : j = bid-FULLT; tile FULLT + j/2; s0 = (j&1)*16; 16 slices
// ---------------------------------------------------------------------------
__global__ void __launch_bounds__(256, 1)
k2_gemm(const float* __restrict__ W, const int* __restrict__ labels) {
    extern __shared__ __align__(1024) char smem[];
    const uint32_t sb = smem_u32(smem);
    const int tid = threadIdx.x;
    const int wid = tid >> 5;
    const int lid = tid & 31;
    const int wm  = wid & 3;        // warp M index (4 x 32 rows per chunk)
    const int wn  = wid >> 2;       // warp N index (2 x 64 classes)

    int tile, s0, nsl;
    if ((int)blockIdx.x < cfg::FULLT) {
        tile = blockIdx.x;  s0 = 0;  nsl = 32;
    } else {
        int j = blockIdx.x - cfg::FULLT;
        tile = cfg::FULLT + (j >> 1);
        s0   = (j & 1) << 4;          // 0 or 16
        nsl  = 16;
    }
    const int cls0 = tile * cfg::NT;
    const int mc0  = s0 >> 3;         // first M-chunk (0 or 2)

    float* sinv = reinterpret_cast<float*>(smem + cfg::SM_INV);

    // ---- prologue: stage A slice s0 + W slice 0 (one commit group) ----
    {
        const char* gsrc = reinterpret_cast<const char*>(g_en16);
#pragma unroll
        for (int q = 0; q < 4; q++) {
            int idx = q * 256 + tid;           // 16B chunk id, 0..1023
            int row = idx >> 3, c8 = idx & 7;
            uint32_t dst = sb + cfg::SM_A + (uint32_t)row * 128
                         + (uint32_t)((c8 ^ (row & 7)) << 4);
            cp_async16(dst, gsrc + ((size_t)(mc0 * 128 + row) * 512 + c8 * 8) * 2);
        }
#pragma unroll
        for (int q = 0; q < 8; q++) {
            int g = q * 256 + tid;             // 16B chunk id, 0..2047
            int row = g >> 4, c = g & 15;
            int cls = cls0 + row;
            bool ok = (cls < cfg::NCLS);
            uint32_t dst = sb + cfg::SM_W + (uint32_t)row * 256
                         + (uint32_t)((c ^ (row & 15)) << 4);
            const float* src = W + (size_t)(ok ? cls : 0) * 512 + c * 4;
            cp_async16z(dst, src, ok ? 16u : 0u);
        }
        cp_commit();
    }

    float wss = 0.0f;      // partial sum-sq: row tid>>1, half tid&1
    uint32_t acc[2][8][2]; // f16x2 accumulators: [mt][nt][row r / r+8]
#pragma unroll
    for (int a = 0; a < 2; a++)
#pragma unroll
        for (int b = 0; b < 8; b++) {
            acc[a][b][0] = 0u; acc[a][b][1] = 0u;
        }

    const int grp = lid >> 2;      // 0..7 (row within 8)
    const int qid = lid & 3;       // quad lane

    // ---- Mainloop: nsl slices (local s; global slice i = s0 + s) ----
    for (int s = 0; s < nsl; s++) {
        const int i  = s0 + s;
        const int kc = i & 7;

        // issue commit group: A slice i+1 (+ W k-slice s+1 while s<7)
        if (s + 1 < nsl) {
            int i2 = i + 1;
            int mc2 = i2 >> 3, kk2 = i2 & 7, bb = i2 & 1;
            const char* gsrc = reinterpret_cast<const char*>(g_en16);
#pragma unroll
            for (int q = 0; q < 4; q++) {
                int idx = q * 256 + tid;
                int row = idx >> 3, c8 = idx & 7;
                uint32_t dst = sb + cfg::SM_A + (uint32_t)bb * 16384
                             + (uint32_t)row * 128
                             + (uint32_t)((c8 ^ (row & 7)) << 4);
                size_t gofs = ((size_t)(mc2 * 128 + row) * 512 + kk2 * 64 + c8 * 8) * 2;
                cp_async16(dst, gsrc + gofs);
            }
            if (s < 7) {
                int ks = s + 1;                 // W k-slice to stage
#pragma unroll
                for (int q = 0; q < 8; q++) {
                    int g = q * 256 + tid;
                    int row = g >> 4, c = g & 15;
                    int cls = cls0 + row;
                    bool ok = (cls < cfg::NCLS);
                    uint32_t dst = sb + cfg::SM_W + (uint32_t)(ks & 1) * 32768
                                 + (uint32_t)row * 256
                                 + (uint32_t)((c ^ (row & 15)) << 4);
                    const float* src = W + (size_t)(ok ? cls : 0) * 512 + ks * 64 + c * 4;
                    cp_async16z(dst, src, ok ? 16u : 0u);
                }
            }
            cp_commit();
            cp_wait<1>();          // previous group (A slice i, W slice s) in
        } else {
            cp_wait<0>();
        }
        __syncthreads();

        // ---- first 8 local slices: convert staged fp32 W -> fp16 B ----
        if (s < 8) {
            const int row = tid >> 1;
            const int hh  = tid & 1;               // half: k [32h, 32h+32)
            const char* wbase = smem + cfg::SM_W + (size_t)(s & 1) * 32768
                              + (size_t)row * 256;
            char* bbase = smem + cfg::SM_B + (size_t)s * 16384 + (size_t)row * 128;
#pragma unroll
            for (int j = 0; j < 8; j++) {
                int c = hh * 8 + j;
                float4 v = *reinterpret_cast<const float4*>(
                    wbase + ((c ^ (row & 15)) << 4));
                wss += v.x * v.x + v.y * v.y + v.z * v.z + v.w * v.w;
                __half2 h0 = __float22half2_rn(make_float2(v.x, v.y));
                __half2 h1 = __float22half2_rn(make_float2(v.z, v.w));
                uint2 pk;
                pk.x = *reinterpret_cast<uint32_t*>(&h0);
                pk.y = *reinterpret_cast<uint32_t*>(&h1);
                *reinterpret_cast<uint2*>(
                    bbase + (((c >> 1) ^ (row & 7)) << 4) + (c & 1) * 8) = pk;
            }
            if (s == 7) {
                float tot = wss + __shfl_xor_sync(0xffffffffu, wss, 1);
                if (hh == 0)
                    sinv[row] = 1.0f / fmaxf(sqrtf(tot), 1e-12f);
            }
            __syncthreads();       // B slice s (and sinv at s=7) visible
        }

        const uint32_t abase = sb + cfg::SM_A + (uint32_t)(i & 1) * 16384;
        const uint32_t bbase = sb + cfg::SM_B + (uint32_t)kc * 16384;

#pragma unroll
        for (int kt = 0; kt < 4; kt++) {       // four k16 steps per 64-K slice
            // A fragments: 2 m-tiles of 16x16
            uint32_t af[2][4];
#pragma unroll
            for (int mt = 0; mt < 2; mt++) {
                int row = wm * 32 + mt * 16 + (lid & 15);
                int c8  = (kt * 2 + (lid >> 4)) ^ (row & 7);
                ldsm_x4(af[mt][0], af[mt][1], af[mt][2], af[mt][3],
                        abase + (uint32_t)row * 128 + (uint32_t)(c8 << 4));
            }
            // B fragments: 4 n-tile-pairs of (16 n x 16 k)
            uint32_t bf[4][4];
#pragma unroll
            for (int np = 0; np < 4; np++) {
                int n   = np * 16 + ((lid >> 4) << 3) + (lid & 7);
                int row = wn * 64 + n;
                int c8  = (kt * 2 + ((lid >> 3) & 1)) ^ (row & 7);
                ldsm_x4(bf[np][0], bf[np][1], bf[np][2], bf[np][3],
                        bbase + (uint32_t)row * 128 + (uint32_t)(c8 << 4));
            }
#pragma unroll
            for (int mt = 0; mt < 2; mt++)
#pragma unroll
                for (int np = 0; np < 4; np++) {
                    mma16816_f16(acc[mt][np * 2],
                                 af[mt][0], af[mt][1], af[mt][2], af[mt][3],
                                 bf[np][0], bf[np][1]);
                    mma16816_f16(acc[mt][np * 2 + 1],
                                 af[mt][0], af[mt][1], af[mt][2], af[mt][3],
                                 bf[np][2], bf[np][3]);
                }
        }
        __syncthreads();           // all reads of A buf[i&1] done

        // ---- per-M-chunk epilogue ----
        if (kc == 7) {
            int mc = i >> 3;
            int row0 = mc * 128 + wm * 32 + grp;   // rows row0(+mt*16), +8
#pragma unroll
            for (int mt = 0; mt < 2; mt++) {
                int ra = row0 + mt * 16;
                int rb = ra + 8;
                int la  = labels[ra];
                int lbv = labels[rb];
                float sa = 0.0f, sbv = 0.0f;
#pragma unroll
                for (int nt = 0; nt < 8; nt++) {
                    int lc = wn * 64 + nt * 8 + qid * 2;
                    float2 iv = *reinterpret_cast<const float2*>(sinv + lc);
                    int cbase = cls0 + lc;
                    float2 va = __half22float2(
                        *reinterpret_cast<__half2*>(&acc[mt][nt][0]));
                    float2 vb = __half22float2(
                        *reinterpret_cast<__half2*>(&acc[mt][nt][1]));
#pragma unroll
                    for (int h = 0; h < 2; h++) {
                        int cls = cbase + h;
                        float ivv = h ? iv.y : iv.x;
                        bool oob = (cls >= cfg::NCLS);
                        float c0 = (h ? va.y : va.x) * ivv;
                        float c2 = (h ? vb.y : vb.x) * ivv;
                        c0 = fminf(fmaxf(c0, -1.0f), 1.0f);
                        c2 = fminf(fmaxf(c2, -1.0f), 1.0f);
                        float e0 = ex2_approx(fmaf(c0, cfg::S_LOG2E, -cfg::S_LOG2E));
                        float e2 = ex2_approx(fmaf(c2, cfg::S_LOG2E, -cfg::S_LOG2E));
                        sa  += (oob || cls == la)  ? 0.0f : e0;
                        sbv += (oob || cls == lbv) ? 0.0f : e2;
                    }
                }
                sa  += __shfl_xor_sync(0xffffffffu, sa, 1);
                sa  += __shfl_xor_sync(0xffffffffu, sa, 2);
                sbv += __shfl_xor_sync(0xffffffffu, sbv, 1);
                sbv += __shfl_xor_sync(0xffffffffu, sbv, 2);
                if (qid == 0) {
                    atomicAdd(&g_rowsum[ra], sa);
                    atomicAdd(&g_rowsum[rb], sbv);
                }
            }
#pragma unroll
            for (int a = 0; a < 2; a++)
#pragma unroll
                for (int b = 0; b < 8; b++) {
                    acc[a][b][0] = 0u; acc[a][b][1] = 0u;
                }
        }
    }
}

// ---------------------------------------------------------------------------
// Kernel 3: finalize — arcface margin on precomputed exact fp32 target +
// single-block loss reduction.
// ---------------------------------------------------------------------------
__global__ void k3_fin(const int* __restrict__ labels,
                       float* __restrict__ out) {
    __shared__ float red[512];
    int r = threadIdx.x;
    int lb = labels[r];
    float nll = 0.0f;
    if (lb >= 0) {
        float tgt = fminf(fmaxf(g_tgt[r], -1.0f), 1.0f);
        float th  = acosf(fminf(fmaxf(tgt, -1.0f + 1e-7f), 1.0f - 1e-7f));
        float nt  = cosf(th + 0.5f);                       // cos(theta + m)
        float et  = exp2f(fmaf(nt, cfg::S_LOG2E, -cfg::S_LOG2E));
        float se  = g_rowsum[r] + et;                      // full shifted sum
        nll = 64.0f + logf(se) - 64.0f * nt;               // lse - target logit
    }
    red[r] = nll;
    __syncthreads();
#pragma unroll
    for (int s = 256; s > 0; s >>= 1) {
        if (r < s) red[r] += red[r + s];
        __syncthreads();
    }
    if (r == 0) out[0] = red[0] * g_invn;
}

// ---------------------------------------------------------------------------
// Launch
// ---------------------------------------------------------------------------
extern "C" void kernel_launch(void* const* d_in, const int* in_sizes, int n_in,
                              void* d_out, int out_size) {
    const float* emb    = (const float*)d_in[0];
    const int*   labels = (const int*)d_in[1];
    const float* W      = (const float*)d_in[2];
    float*       out    = (float*)d_out;

    cudaFuncSetAttribute(k2_gemm, cudaFuncAttributeMaxDynamicSharedMemorySize,
                         cfg::SM_TOT);

    k1_norm<<<128, 256>>>(emb, W, labels);
    k2_gemm<<<cfg::GRID2, 256, cfg::SM_TOT>>>(W, labels);
    k3_fin<<<1, 512>>>(labels, out);
}

// round 17
// speedup vs baseline: 1.0241x; 1.0019x over previous
#include <cuda_runtime.h>
#include <cuda_fp16.h>
#include <cstdint>

#define DEVI __device__ __forceinline__

// ---------------------------------------------------------------------------
// Problem constants
// ---------------------------------------------------------------------------
namespace cfg {
constexpr int BROWS = 512;      // batch (GEMM M)
constexpr int DIM   = 512;      // embedding dim (GEMM K)
constexpr int NCLS  = 200000;   // classes (GEMM N, tiled)
constexpr int NT    = 128;      // classes per CTA tile
constexpr int NTILE = (NCLS + NT - 1) / NT;   // 1563
constexpr int FULLT = 1480;                   // tiles done by single CTAs
constexpr int GRID2 = FULLT + 2 * (NTILE - FULLT);  // 1646

// smem layout (bytes, within dynamic smem)
constexpr int SM_INV = 0;                     // 128 floats: 1/||w||
constexpr int SM_B   = 1024;                  // 8 K-slices x 128 rows x 128B f16
constexpr int SM_A   = SM_B + 131072;         // 2 bufs x 128 rows x 128B f16
constexpr int SM_W   = SM_A + 32768;          // 2 bufs x 128 rows x 256B fp32
constexpr int SM_TOT = SM_W + 65536;          // 230400

constexpr float S_LOG2E = 92.33248261689366f; // 64 * log2(e)
}

// ---------------------------------------------------------------------------
// Device scratch (no allocations allowed)
// ---------------------------------------------------------------------------
__device__ __align__(16) float  g_en32[cfg::BROWS * cfg::DIM]; // norm emb fp32
__device__ __align__(16) __half g_en16[cfg::BROWS * cfg::DIM]; // norm emb fp16
__device__ float g_rowsum[cfg::BROWS];   // sum exp(l-64), excl target
__device__ float g_invn;                 // 1/n_valid

// ---------------------------------------------------------------------------
// PTX helpers (base-ISA only: legal on sm_103 / compute_103)
// ---------------------------------------------------------------------------
DEVI uint32_t smem_u32(const void* p) {
    uint32_t a;
    asm("{ .reg .u64 t; cvta.to.shared.u64 t, %1; cvt.u32.u64 %0, t; }"
        : "=r"(a) : "l"(p));
    return a;
}

DEVI float ex2_approx(float x) {
    float r;
    asm("ex2.approx.ftz.f32 %0, %1;" : "=f"(r) : "f"(x));
    return r;
}

DEVI void cp_async16(uint32_t dst, const void* src) {
    asm volatile("cp.async.cg.shared.global [%0], [%1], 16;"
                 :: "r"(dst), "l"(src) : "memory");
}
DEVI void cp_async16z(uint32_t dst, const void* src, uint32_t nbytes) {
    asm volatile("cp.async.cg.shared.global [%0], [%1], 16, %2;"
                 :: "r"(dst), "l"(src), "r"(nbytes) : "memory");
}
DEVI void cp_commit() { asm volatile("cp.async.commit_group;" ::: "memory"); }
template <int N> DEVI void cp_wait() {
    asm volatile("cp.async.wait_group %0;" :: "n"(N) : "memory");
}

DEVI void ldsm_x4(uint32_t& r0, uint32_t& r1, uint32_t& r2, uint32_t& r3,
                  uint32_t addr) {
    asm volatile("ldmatrix.sync.aligned.m8n8.x4.shared.b16 {%0,%1,%2,%3}, [%4];"
                 : "=r"(r0), "=r"(r1), "=r"(r2), "=r"(r3) : "r"(addr));
}

// fp16 tensor-core MMA with fp16 accumulate
DEVI void mma16816_f16(uint32_t* d, uint32_t a0, uint32_t a1, uint32_t a2,
                       uint32_t a3, uint32_t b0, uint32_t b1) {
    asm volatile(
        "mma.sync.aligned.m16n8k16.row.col.f16.f16.f16.f16 "
        "{%0,%1}, {%2,%3,%4,%5}, {%6,%7}, {%0,%1};"
        : "+r"(d[0]), "+r"(d[1])
        : "r"(a0), "r"(a1), "r"(a2), "r"(a3), "r"(b0), "r"(b1));
}

// ---------------------------------------------------------------------------
// Kernel 1: normalize embeddings -> fp32 + fp16 copies (warp per row).
// Block 0 additionally does the k0 prep work (zero rowsums, count valid).
// ---------------------------------------------------------------------------
__global__ void k1_norm(const float* __restrict__ emb,
                        const int* __restrict__ labels,
                        float* __restrict__ out) {
    __shared__ int part[8];
    int gw  = blockIdx.x * 8 + (threadIdx.x >> 5);
    int lid = threadIdx.x & 31;
    const float4* src = reinterpret_cast<const float4*>(emb) + (size_t)gw * 128;
    float4 v[4];
    float ss = 0.0f;
#pragma unroll
    for (int j = 0; j < 4; j++) {
        v[j] = src[j * 32 + lid];
        ss += v[j].x * v[j].x + v[j].y * v[j].y + v[j].z * v[j].z + v[j].w * v[j].w;
    }
#pragma unroll
    for (int s = 16; s > 0; s >>= 1) ss += __shfl_xor_sync(0xffffffffu, ss, s);
    float inv = 1.0f / fmaxf(sqrtf(ss), 1e-12f);

    float4* d32 = reinterpret_cast<float4*>(g_en32) + (size_t)gw * 128;
    uint2*  d16 = reinterpret_cast<uint2*>(g_en16) + (size_t)gw * 128;
#pragma unroll
    for (int j = 0; j < 4; j++) {
        float4 n = make_float4(v[j].x * inv, v[j].y * inv, v[j].z * inv, v[j].w * inv);
        d32[j * 32 + lid] = n;
        __half2 h0 = __float22half2_rn(make_float2(n.x, n.y));
        __half2 h1 = __float22half2_rn(make_float2(n.z, n.w));
        uint2 pk;
        pk.x = *reinterpret_cast<uint32_t*>(&h0);
        pk.y = *reinterpret_cast<uint32_t*>(&h1);
        d16[j * 32 + lid] = pk;
    }

    // ---- fused prep (block 0 only) ----
    if (blockIdx.x == 0) {
        int t = threadIdx.x;
        g_rowsum[t] = 0.0f;
        g_rowsum[t + 256] = 0.0f;
        int c = (labels[t] >= 0) + (labels[t + 256] >= 0);
#pragma unroll
        for (int s = 16; s > 0; s >>= 1) c += __shfl_xor_sync(0xffffffffu, c, s);
        if (lid == 0) part[t >> 5] = c;
        __syncthreads();
        if (t == 0) {
            int tot = 0;
#pragma unroll
            for (int j = 0; j < 8; j++) tot += part[j];
            g_invn = 1.0f / fmaxf((float)tot, 1.0f);
            out[0] = 0.0f;
        }
    }
}

// ---------------------------------------------------------------------------
// Kernel 2: fused fp16 mma.sync (f16 acc) GEMM + softmax-denominator
// epilogue, with tail-wave splitting:
//   bid <  FULLT : tile bid, slices 0..31 (all 4 M-chunks)
//   bid >= FULLT : j = bid-FULLT; tile FULLT + j/2; s0 = (j&1)*16; 16 slices
// Each CTA converts its own W tile (fp32 staged via cp.async in the same
// commit groups as A slices) during its FIRST 8 slices; true fp32 1/||w||
// finalized at local slice 7. Tail halves re-read W for their tile (cheap).
// ---------------------------------------------------------------------------
__global__ void __launch_bounds__(256, 1)
k2_gemm(const float* __restrict__ W, const int* __restrict__ labels) {
    extern __shared__ __align__(1024) char smem[];
    const uint32_t sb = smem_u32(smem);
    const int tid = threadIdx.x;
    const int wid = tid >> 5;
    const int lid = tid & 31;
    const int wm  = wid & 3;        // warp M index (4 x 32 rows per chunk)
    const int wn  = wid >> 2;       // warp N index (2 x 64 classes)

    int tile, s0, nsl;
    if ((int)blockIdx.x < cfg::FULLT) {
        tile = blockIdx.x;  s0 = 0;  nsl = 32;
    } else {
        int j = blockIdx.x - cfg::FULLT;
        tile = cfg::FULLT + (j >> 1);
        s0   = (j & 1) << 4;          // 0 or 16
        nsl  = 16;
    }
    const int cls0 = tile * cfg::NT;
    const int mc0  = s0 >> 3;         // first M-chunk (0 or 2)

    float* sinv = reinterpret_cast<float*>(smem + cfg::SM_INV);

    // ---- prologue: stage A slice s0 + W slice 0 (one commit group) ----
    {
        const char* gsrc = reinterpret_cast<const char*>(g_en16);
#pragma unroll
        for (int q = 0; q < 4; q++) {
            int idx = q * 256 + tid;           // 16B chunk id, 0..1023
            int row = idx >> 3, c8 = idx & 7;
            uint32_t dst = sb + cfg::SM_A + (uint32_t)row * 128
                         + (uint32_t)((c8 ^ (row & 7)) << 4);
            cp_async16(dst, gsrc + ((size_t)(mc0 * 128 + row) * 512 + c8 * 8) * 2);
        }
#pragma unroll
        for (int q = 0; q < 8; q++) {
            int g = q * 256 + tid;             // 16B chunk id, 0..2047
            int row = g >> 4, c = g & 15;
            int cls = cls0 + row;
            bool ok = (cls < cfg::NCLS);
            uint32_t dst = sb + cfg::SM_W + (uint32_t)row * 256
                         + (uint32_t)((c ^ (row & 15)) << 4);
            const float* src = W + (size_t)(ok ? cls : 0) * 512 + c * 4;
            cp_async16z(dst, src, ok ? 16u : 0u);
        }
        cp_commit();
    }

    float wss = 0.0f;      // partial sum-sq: row tid>>1, half tid&1
    uint32_t acc[2][8][2]; // f16x2 accumulators: [mt][nt][row r / r+8]
#pragma unroll
    for (int a = 0; a < 2; a++)
#pragma unroll
        for (int b = 0; b < 8; b++) {
            acc[a][b][0] = 0u; acc[a][b][1] = 0u;
        }

    const int grp = lid >> 2;      // 0..7 (row within 8)
    const int qid = lid & 3;       // quad lane

    // ---- Mainloop: nsl slices (local s; global slice i = s0 + s) ----
    for (int s = 0; s < nsl; s++) {
        const int i  = s0 + s;
        const int kc = i & 7;

        // issue commit group: A slice i+1 (+ W k-slice s+1 while s<7)
        if (s + 1 < nsl) {
            int i2 = i + 1;
            int mc2 = i2 >> 3, kk2 = i2 & 7, bb = i2 & 1;
            const char* gsrc = reinterpret_cast<const char*>(g_en16);
#pragma unroll
            for (int q = 0; q < 4; q++) {
                int idx = q * 256 + tid;
                int row = idx >> 3, c8 = idx & 7;
                uint32_t dst = sb + cfg::SM_A + (uint32_t)bb * 16384
                             + (uint32_t)row * 128
                             + (uint32_t)((c8 ^ (row & 7)) << 4);
                size_t gofs = ((size_t)(mc2 * 128 + row) * 512 + kk2 * 64 + c8 * 8) * 2;
                cp_async16(dst, gsrc + gofs);
            }
            if (s < 7) {
                int ks = s + 1;                 // W k-slice to stage
#pragma unroll
                for (int q = 0; q < 8; q++) {
                    int g = q * 256 + tid;
                    int row = g >> 4, c = g & 15;
                    int cls = cls0 + row;
                    bool ok = (cls < cfg::NCLS);
                    uint32_t dst = sb + cfg::SM_W + (uint32_t)(ks & 1) * 32768
                                 + (uint32_t)row * 256
                                 + (uint32_t)((c ^ (row & 15)) << 4);
                    const float* src = W + (size_t)(ok ? cls : 0) * 512 + ks * 64 + c * 4;
                    cp_async16z(dst, src, ok ? 16u : 0u);
                }
            }
            cp_commit();
            cp_wait<1>();          // previous group (A slice i, W slice s) in
        } else {
            cp_wait<0>();
        }
        __syncthreads();

        // ---- first 8 local slices: convert staged fp32 W -> fp16 B ----
        if (s < 8) {
            const int row = tid >> 1;
            const int hh  = tid & 1;               // half: k [32h, 32h+32)
            const char* wbase = smem + cfg::SM_W + (size_t)(s & 1) * 32768
                              + (size_t)row * 256;
            char* bbase = smem + cfg::SM_B + (size_t)s * 16384 + (size_t)row * 128;
#pragma unroll
            for (int j = 0; j < 8; j++) {
                int c = hh * 8 + j;
                float4 v = *reinterpret_cast<const float4*>(
                    wbase + ((c ^ (row & 15)) << 4));
                wss += v.x * v.x + v.y * v.y + v.z * v.z + v.w * v.w;
                __half2 h0 = __float22half2_rn(make_float2(v.x, v.y));
                __half2 h1 = __float22half2_rn(make_float2(v.z, v.w));
                uint2 pk;
                pk.x = *reinterpret_cast<uint32_t*>(&h0);
                pk.y = *reinterpret_cast<uint32_t*>(&h1);
                *reinterpret_cast<uint2*>(
                    bbase + (((c >> 1) ^ (row & 7)) << 4) + (c & 1) * 8) = pk;
            }
            if (s == 7) {
                float tot = wss + __shfl_xor_sync(0xffffffffu, wss, 1);
                if (hh == 0)
                    sinv[row] = 1.0f / fmaxf(sqrtf(tot), 1e-12f);
            }
            __syncthreads();       // B slice s (and sinv at s=7) visible
        }

        const uint32_t abase = sb + cfg::SM_A + (uint32_t)(i & 1) * 16384;
        const uint32_t bbase = sb + cfg::SM_B + (uint32_t)kc * 16384;

#pragma unroll
        for (int kt = 0; kt < 4; kt++) {       // four k16 steps per 64-K slice
            // A fragments: 2 m-tiles of 16x16
            uint32_t af[2][4];
#pragma unroll
            for (int mt = 0; mt < 2; mt++) {
                int row = wm * 32 + mt * 16 + (lid & 15);
                int c8  = (kt * 2 + (lid >> 4)) ^ (row & 7);
                ldsm_x4(af[mt][0], af[mt][1], af[mt][2], af[mt][3],
                        abase + (uint32_t)row * 128 + (uint32_t)(c8 << 4));
            }
            // B fragments: 4 n-tile-pairs of (16 n x 16 k)
            uint32_t bf[4][4];
#pragma unroll
            for (int np = 0; np < 4; np++) {
                int n   = np * 16 + ((lid >> 4) << 3) + (lid & 7);
                int row = wn * 64 + n;
                int c8  = (kt * 2 + ((lid >> 3) & 1)) ^ (row & 7);
                ldsm_x4(bf[np][0], bf[np][1], bf[np][2], bf[np][3],
                        bbase + (uint32_t)row * 128 + (uint32_t)(c8 << 4));
            }
#pragma unroll
            for (int mt = 0; mt < 2; mt++)
#pragma unroll
                for (int np = 0; np < 4; np++) {
                    mma16816_f16(acc[mt][np * 2],
                                 af[mt][0], af[mt][1], af[mt][2], af[mt][3],
                                 bf[np][0], bf[np][1]);
                    mma16816_f16(acc[mt][np * 2 + 1],
                                 af[mt][0], af[mt][1], af[mt][2], af[mt][3],
                                 bf[np][2], bf[np][3]);
                }
        }
        __syncthreads();           // all reads of A buf[i&1] done

        // ---- per-M-chunk epilogue ----
        if (kc == 7) {
            int mc = i >> 3;
            int row0 = mc * 128 + wm * 32 + grp;   // rows row0(+mt*16), +8
#pragma unroll
            for (int mt = 0; mt < 2; mt++) {
                int ra = row0 + mt * 16;
                int rb = ra + 8;
                int la  = labels[ra];
                int lbv = labels[rb];
                float sa = 0.0f, sbv = 0.0f;
#pragma unroll
                for (int nt = 0; nt < 8; nt++) {
                    int lc = wn * 64 + nt * 8 + qid * 2;
                    float2 iv = *reinterpret_cast<const float2*>(sinv + lc);
                    int cbase = cls0 + lc;
                    float2 va = __half22float2(
                        *reinterpret_cast<__half2*>(&acc[mt][nt][0]));
                    float2 vb = __half22float2(
                        *reinterpret_cast<__half2*>(&acc[mt][nt][1]));
#pragma unroll
                    for (int h = 0; h < 2; h++) {
                        int cls = cbase + h;
                        float ivv = h ? iv.y : iv.x;
                        bool oob = (cls >= cfg::NCLS);
                        float c0 = (h ? va.y : va.x) * ivv;
                        float c2 = (h ? vb.y : vb.x) * ivv;
                        c0 = fminf(fmaxf(c0, -1.0f), 1.0f);
                        c2 = fminf(fmaxf(c2, -1.0f), 1.0f);
                        float e0 = ex2_approx(fmaf(c0, cfg::S_LOG2E, -cfg::S_LOG2E));
                        float e2 = ex2_approx(fmaf(c2, cfg::S_LOG2E, -cfg::S_LOG2E));
                        sa  += (oob || cls == la)  ? 0.0f : e0;
                        sbv += (oob || cls == lbv) ? 0.0f : e2;
                    }
                }
                sa  += __shfl_xor_sync(0xffffffffu, sa, 1);
                sa  += __shfl_xor_sync(0xffffffffu, sa, 2);
                sbv += __shfl_xor_sync(0xffffffffu, sbv, 1);
                sbv += __shfl_xor_sync(0xffffffffu, sbv, 2);
                if (qid == 0) {
                    atomicAdd(&g_rowsum[ra], sa);
                    atomicAdd(&g_rowsum[rb], sbv);
                }
            }
#pragma unroll
            for (int a = 0; a < 2; a++)
#pragma unroll
                for (int b = 0; b < 8; b++) {
                    acc[a][b][0] = 0u; acc[a][b][1] = 0u;
                }
        }
    }
}

// ---------------------------------------------------------------------------
// Kernel 3: finalize — exact fp32 target logit with arcface margin + loss
// ---------------------------------------------------------------------------
__global__ void k3_fin(const float* __restrict__ W,
                       const int* __restrict__ labels,
                       float* __restrict__ out) {
    int wid = threadIdx.x >> 5, lid = threadIdx.x & 31;
    int row = blockIdx.x * 8 + wid;
    int lb = labels[row];
    if (lb < 0) return;   // invalid row: excluded from mean

    const float4* er = reinterpret_cast<const float4*>(g_en32) + (size_t)row * 128;
    const float4* wr = reinterpret_cast<const float4*>(W) + (size_t)lb * 128;
    float dot = 0.0f, ww = 0.0f;
#pragma unroll
    for (int j = 0; j < 4; j++) {
        float4 e = er[j * 32 + lid];
        float4 w = wr[j * 32 + lid];
        dot += e.x * w.x + e.y * w.y + e.z * w.z + e.w * w.w;
        ww  += w.x * w.x + w.y * w.y + w.z * w.z + w.w * w.w;
    }
#pragma unroll
    for (int s = 16; s > 0; s >>= 1) {
        dot += __shfl_xor_sync(0xffffffffu, dot, s);
        ww  += __shfl_xor_sync(0xffffffffu, ww, s);
    }
    if (lid == 0) {
        float wn   = fmaxf(sqrtf(ww), 1e-12f);
        float cosr = dot / wn;
        float tgt  = fminf(fmaxf(cosr, -1.0f), 1.0f);
        float th   = acosf(fminf(fmaxf(tgt, -1.0f + 1e-7f), 1.0f - 1e-7f));
        float nt   = cosf(th + 0.5f);                       // cos(theta + m)
        float et   = exp2f(fmaf(nt, cfg::S_LOG2E, -cfg::S_LOG2E));
        float se   = g_rowsum[row] + et;                    // full shifted sum
        float nll  = 64.0f + logf(se) - 64.0f * nt;         // lse - target logit
        atomicAdd(out, nll * g_invn);
    }
}

// ---------------------------------------------------------------------------
// Launch
// ---------------------------------------------------------------------------
extern "C" void kernel_launch(void* const* d_in, const int* in_sizes, int n_in,
                              void* d_out, int out_size) {
    const float* emb    = (const float*)d_in[0];
    const int*   labels = (const int*)d_in[1];
    const float* W      = (const float*)d_in[2];
    float*       out    = (float*)d_out;

    cudaFuncSetAttribute(k2_gemm, cudaFuncAttributeMaxDynamicSharedMemorySize,
                         cfg::SM_TOT);

    k1_norm<<<64, 256>>>(emb, labels, out);
    k2_gemm<<<cfg::GRID2, 256, cfg::SM_TOT>>>(W, labels);
    k3_fin<<<64, 256>>>(W, labels, out);
}